// round 17
// baseline (speedup 1.0000x reference)
#include <cuda_runtime.h>
#include <cuda_pipeline.h>
#include <math.h>
#include <stdint.h>

#define T_STEPS 1000
#define BATCH   64
#define IN_DIM  512
#define HID     1024
#define OUT_DIM 64
#define NY      65
#define E_SZ    819
#define ALPHA   0.2f
#define OMALPHA 0.8f
#define NCTA 128
#define OPAD 80
#define WSTR 1028            // j-row stride (floats) for weights AND staging

__device__ float g_xq[(size_t)T_STEPS * BATCH * HID];     // [t][b][h]
__device__ float g_outAll[(size_t)T_STEPS * HID * BATCH]; // [t][j][b]  (readout)
__device__ float g_outT[(size_t)T_STEPS * BATCH * HID];   // [t][b][j]  (rnn broadcast)
__device__ float g_eWhP2[32 * 32 * WSTR];                 // [hgrp][h&31][j pad]
__device__ float g_eWoT[HID * OPAD];                      // [j][o]
__device__ unsigned g_bar[8 * 64];                        // per-b-quarter count/flag (1000 flips, even)

__device__ __forceinline__ unsigned atom_add_release(unsigned* p, unsigned v) {
    unsigned r;
    asm volatile("atom.add.release.gpu.global.u32 %0, [%1], %2;"
                 : "=r"(r) : "l"(p), "r"(v) : "memory");
    return r;
}
__device__ __forceinline__ void st_relaxed(unsigned* p, unsigned v) {
    asm volatile("st.relaxed.gpu.global.u32 [%0], %1;" :: "l"(p), "r"(v) : "memory");
}
__device__ __forceinline__ void st_release(unsigned* p, unsigned v) {
    asm volatile("st.release.gpu.global.u32 [%0], %1;" :: "l"(p), "r"(v) : "memory");
}
__device__ __forceinline__ unsigned ld_acquire(unsigned* p) {
    unsigned r;
    asm volatile("ld.acquire.gpu.global.u32 %0, [%1];" : "=r"(r) : "l"(p) : "memory");
    return r;
}

__device__ __forceinline__ unsigned long long pk2(float x, float y) {
    unsigned long long r;
    asm("mov.b64 %0, {%1, %2};" : "=l"(r) : "r"(__float_as_uint(x)), "r"(__float_as_uint(y)));
    return r;
}
__device__ __forceinline__ void upk2(unsigned long long v, float &x, float &y) {
    unsigned xi, yi;
    asm("mov.b64 {%0, %1}, %2;" : "=r"(xi), "=r"(yi) : "l"(v));
    x = __uint_as_float(xi); y = __uint_as_float(yi);
}
__device__ __forceinline__ unsigned long long ffma2(unsigned long long a,
                                                    unsigned long long b,
                                                    unsigned long long c) {
    unsigned long long d;
    asm("fma.rn.f32x2 %0, %1, %2, %3;" : "=l"(d) : "l"(a), "l"(b), "l"(c));
    return d;
}

__global__ void noop_kernel() {}

__global__ void prep_kernel(const float* __restrict__ Wh,
                            const float* __restrict__ Wo,
                            const float* __restrict__ Wv) {
    int idx = blockIdx.x * blockDim.x + threadIdx.x;
    const int N1 = HID * HID;
    if (idx < N1) {
        int h = idx >> 10, j = idx & 1023;
        float v = Wh[idx];
        v = v > 0.f ? v : 0.f;
        float s = (j < E_SZ) ? 1.f : -1.f;
        v = (h == j) ? 0.f : v * s;
        g_eWhP2[(size_t)(h >> 5) * (32 * WSTR) + (size_t)(h & 31) * WSTR + j] = v;
    } else if (idx < N1 + NY * HID) {
        int i2 = idx - N1;
        int o = i2 >> 10, j = i2 & 1023;
        float v = (o < OUT_DIM) ? Wo[o * HID + j] : Wv[j];
        v = v > 0.f ? v : 0.f;
        if (j >= E_SZ) v = 0.f;
        g_eWoT[(size_t)j * OPAD + o] = v;
    }
}

// ---- phase 1 (proven): g_xq[t][b][h] = sum_k x[t][b][k]*relu(Wx[h][k])
__global__ __launch_bounds__(256) void xproj_kernel(const float* __restrict__ x,
                                                    const float* __restrict__ Wx) {
    __shared__ float As[16][64];
    __shared__ float Bs[16][128];
    const int t  = blockIdx.y;
    const int h0 = blockIdx.x * 128;
    const int tid = threadIdx.x;
    const int tx = tid & 15;
    const int ty = tid >> 4;

    unsigned long long acc[4][4];
#pragma unroll
    for (int i = 0; i < 4; i++)
#pragma unroll
        for (int p = 0; p < 4; p++) acc[i][p] = 0ull;

    const float* xb = x + (size_t)t * BATCH * IN_DIM;
    const int bb  = tid >> 2;
    const int kk4 = (tid & 3) << 2;
    const int hh  = tid & 127;
    const int kq  = (tid >> 7) << 3;

    for (int k0 = 0; k0 < IN_DIM; k0 += 16) {
        __syncthreads();
        float4 av = *(const float4*)&xb[(size_t)bb * IN_DIM + k0 + kk4];
        As[kk4 + 0][bb] = av.x; As[kk4 + 1][bb] = av.y;
        As[kk4 + 2][bb] = av.z; As[kk4 + 3][bb] = av.w;
        const float* wrow = Wx + (size_t)(h0 + hh) * IN_DIM + k0 + kq;
        float4 w0 = *(const float4*)wrow;
        float4 w1 = *(const float4*)(wrow + 4);
        Bs[kq + 0][hh] = fmaxf(w0.x, 0.f); Bs[kq + 1][hh] = fmaxf(w0.y, 0.f);
        Bs[kq + 2][hh] = fmaxf(w0.z, 0.f); Bs[kq + 3][hh] = fmaxf(w0.w, 0.f);
        Bs[kq + 4][hh] = fmaxf(w1.x, 0.f); Bs[kq + 5][hh] = fmaxf(w1.y, 0.f);
        Bs[kq + 6][hh] = fmaxf(w1.z, 0.f); Bs[kq + 7][hh] = fmaxf(w1.w, 0.f);
        __syncthreads();
#pragma unroll
        for (int kk = 0; kk < 16; kk++) {
            float4 a = *(const float4*)&As[kk][tx << 2];
            ulonglong2 wA = *(const ulonglong2*)&Bs[kk][(ty << 3)];
            ulonglong2 wB = *(const ulonglong2*)&Bs[kk][(ty << 3) + 4];
            unsigned long long a0 = pk2(a.x, a.x), a1 = pk2(a.y, a.y);
            unsigned long long a2 = pk2(a.z, a.z), a3 = pk2(a.w, a.w);
            acc[0][0] = ffma2(a0, wA.x, acc[0][0]); acc[0][1] = ffma2(a0, wA.y, acc[0][1]);
            acc[0][2] = ffma2(a0, wB.x, acc[0][2]); acc[0][3] = ffma2(a0, wB.y, acc[0][3]);
            acc[1][0] = ffma2(a1, wA.x, acc[1][0]); acc[1][1] = ffma2(a1, wA.y, acc[1][1]);
            acc[1][2] = ffma2(a1, wB.x, acc[1][2]); acc[1][3] = ffma2(a1, wB.y, acc[1][3]);
            acc[2][0] = ffma2(a2, wA.x, acc[2][0]); acc[2][1] = ffma2(a2, wA.y, acc[2][1]);
            acc[2][2] = ffma2(a2, wB.x, acc[2][2]); acc[2][3] = ffma2(a2, wB.y, acc[2][3]);
            acc[3][0] = ffma2(a3, wA.x, acc[3][0]); acc[3][1] = ffma2(a3, wA.y, acc[3][1]);
            acc[3][2] = ffma2(a3, wB.x, acc[3][2]); acc[3][3] = ffma2(a3, wB.y, acc[3][3]);
        }
    }
    float* xqT = g_xq + (size_t)t * (BATCH * HID);
#pragma unroll
    for (int i = 0; i < 4; i++) {
        int b = (tx << 2) + i;
#pragma unroll
        for (int p = 0; p < 4; p++) {
            float f0, f1; upk2(acc[i][p], f0, f1);
            int h = h0 + (ty << 3) + (p << 1);
            float2 v2 = make_float2(f0, f1);
            *(float2*)&xqT[(size_t)b * HID + h] = v2;
        }
    }
}

// ---- group barrier: 32 CTAs sharing one b-quarter (proven) ----
__device__ __forceinline__ void group_barrier(unsigned &sense, int grp) {
    sense ^= 1u;
    __syncthreads();
    if (threadIdx.x == 0) {
        unsigned* cnt  = &g_bar[grp * 64];
        unsigned* flag = &g_bar[(4 + grp) * 64];
        unsigned old = atom_add_release(cnt, 1u);
        if (old == 31u) {
            st_relaxed(cnt, 0u);
            st_release(flag, sense);
        } else {
            while (ld_acquire(flag) != sense) { }
        }
    }
    __syncthreads();
}

// ---- phase 2: persistent recurrence, 8h x 8b register tile, 256 threads ----
// 128 CTAs x 256 threads (255-reg budget -> ~220 live regs, no spill).
// CTA = (hgrp 32h, b-quarter 16b). Weights [32][1028] resident in smem.
// Warp w (8 warps) owns j-window [w*128, w*128+128): stages its own 16b x 128j
// slice via cp.async (wait + __syncwarp only; producer == consumer warp).
// Lane: jsub = lane>>3 (32j sub-window), ht = (lane>>1)&3, bt = lane&1.
// Thread tile: h [ht*8, +8) x b [bt*8, +8) x 32j. Per q(4j): 16 LDS.128 serve
// 256 FMA (2x fewer crossbar wavefronts than 4h x 4b). 32-way reduction with
// fp32 partials (in-thread f32x2 lane-sum first) in sRedF aliasing dead staging.
extern __shared__ float rnn_smem[];
__global__ __launch_bounds__(256, 1) void rnn_kernel(const float* __restrict__ bh) {
    float* sW = rnn_smem;                                // [32][1028]
    float* sA = rnn_smem + 32 * WSTR;                    // [16][1028] staging
    float* sRedF = sA;                                   // [32][512] fp32 = 65536 B (aliases sA)
    float* sOv = rnn_smem + 48 * WSTR;                   // [32][17] extension, disjoint

    const int cta = blockIdx.x;
    const int tid = threadIdx.x;
    const int hgrp = cta >> 2;
    const int bqg = cta & 3;
    const int b0 = bqg * 16;
    const int lane = tid & 31;
    const int w = tid >> 5;              // warp id 0..7, j-window 128j
    const int jsub = lane >> 3;          // 0..3, 32j sub-window
    const int ht = (lane >> 1) & 3;      // h-tile 0..3 (8 h each)
    const int bt = lane & 1;             // b-tile 0..1 (8 b each)
    const int jgrp = w * 4 + jsub;       // 0..31 reduction group
    // epilogue: thread owns outputs oid = tid and tid+256 (oid = b_l*32 + h_l)
    const int h_own = tid & 31;
    const int b_own0 = tid >> 5;         // 0..7
    const int hOutG = hgrp * 32 + h_own;
    const int bOut0 = b0 + b_own0;
    const int bOut1 = b0 + b_own0 + 8;

    {   // resident weights, once per launch
        const float4* src = (const float4*)(g_eWhP2 + (size_t)hgrp * (32 * WSTR));
        float4* dst = (float4*)sW;
        for (int i = tid; i < 32 * WSTR / 4; i += 256) dst[i] = src[i];
    }

    const float bhv = bh[hOutG];
    unsigned sense = 0;
    float st0, st1;
    {   // step 0: out_prev == 0
        float xq0 = g_xq[(size_t)bOut0 * HID + hOutG];
        float xq1 = g_xq[(size_t)bOut1 * HID + hOutG];
        st0 = ALPHA * (xq0 + bhv);
        st1 = ALPHA * (xq1 + bhv);
        float ov0 = tanhf(fmaxf(st0, 0.f));
        float ov1 = tanhf(fmaxf(st1, 0.f));
        g_outT[(size_t)bOut0 * HID + hOutG] = ov0;
        g_outT[(size_t)bOut1 * HID + hOutG] = ov1;
        g_outAll[(size_t)hOutG * 64 + bOut0] = ov0;
        g_outAll[(size_t)hOutG * 64 + bOut1] = ov1;
    }
    group_barrier(sense, bqg);   // also orders sW staging

    const int jw = w * 128 + jsub * 32;  // thread's 32-j base
    const float* wBase = sW + (size_t)(ht * 8) * WSTR + jw;
    const float* aBase = sA + (size_t)(bt * 8) * WSTR + jw;

    for (int t = 1; t < T_STEPS; t++) {
        {   // warp-private staging of 16b x 128j window (16 x 16B per lane)
            const float* srcB = g_outT + (size_t)(t - 1) * (BATCH * HID)
                              + (size_t)b0 * HID + w * 128 + lane * 4;
            float* dstB = sA + (size_t)0 * WSTR + w * 128 + lane * 4;
#pragma unroll
            for (int k = 0; k < 16; k++)
                __pipeline_memcpy_async(dstB + (size_t)k * WSTR,
                                        srcB + (size_t)k * HID, 16);
            __pipeline_commit();
        }
        float xq0 = g_xq[(size_t)t * (BATCH * HID) + (size_t)bOut0 * HID + hOutG];
        float xq1 = g_xq[(size_t)t * (BATCH * HID) + (size_t)bOut1 * HID + hOutG];

        unsigned long long acc[8][8];
#pragma unroll
        for (int r = 0; r < 8; r++)
#pragma unroll
            for (int c = 0; c < 8; c++) acc[r][c] = 0ull;

        __pipeline_wait_prior(0);    // own chunks staged
        __syncwarp();                // whole warp's window staged

#pragma unroll 1
        for (int q = 0; q < 8; q++) {
            ulonglong2 wv[8], av[8];
#pragma unroll
            for (int r = 0; r < 8; r++)
                wv[r] = *(const ulonglong2*)(wBase + (size_t)r * WSTR + q * 4);
#pragma unroll
            for (int c = 0; c < 8; c++)
                av[c] = *(const ulonglong2*)(aBase + (size_t)c * WSTR + q * 4);
#pragma unroll
            for (int r = 0; r < 8; r++)
#pragma unroll
                for (int c = 0; c < 8; c++) {
                    acc[r][c] = ffma2(av[c].x, wv[r].x, acc[r][c]);
                    acc[r][c] = ffma2(av[c].y, wv[r].y, acc[r][c]);
                }
        }

        __syncthreads();   // ALL warps done reading sA (sRedF aliases it)
        // in-thread lane sum -> fp32 partials; sRedF[jgrp][b_l*32 + h_l]
#pragma unroll
        for (int c = 0; c < 8; c++) {
            float4 v0, v1;
            {
                float f0, f1;
                upk2(acc[0][c], f0, f1); v0.x = f0 + f1;
                upk2(acc[1][c], f0, f1); v0.y = f0 + f1;
                upk2(acc[2][c], f0, f1); v0.z = f0 + f1;
                upk2(acc[3][c], f0, f1); v0.w = f0 + f1;
                upk2(acc[4][c], f0, f1); v1.x = f0 + f1;
                upk2(acc[5][c], f0, f1); v1.y = f0 + f1;
                upk2(acc[6][c], f0, f1); v1.z = f0 + f1;
                upk2(acc[7][c], f0, f1); v1.w = f0 + f1;
            }
            int base = jgrp * 512 + (bt * 8 + c) * 32 + ht * 8;
            *(float4*)&sRedF[base]     = v0;
            *(float4*)&sRedF[base + 4] = v1;
        }
        __syncthreads();
        float s0 = sRedF[tid], s1 = sRedF[tid + 256];
#pragma unroll
        for (int g = 1; g < 32; g++) {
            s0 += sRedF[g * 512 + tid];
            s1 += sRedF[g * 512 + tid + 256];
        }

        st0 = OMALPHA * st0 + ALPHA * (xq0 + s0 + bhv);
        st1 = OMALPHA * st1 + ALPHA * (xq1 + s1 + bhv);
        float ov0 = tanhf(fmaxf(st0, 0.f));
        float ov1 = tanhf(fmaxf(st1, 0.f));
        g_outT[(size_t)t * (BATCH * HID) + (size_t)bOut0 * HID + hOutG] = ov0;
        g_outT[(size_t)t * (BATCH * HID) + (size_t)bOut1 * HID + hOutG] = ov1;
        sOv[h_own * 17 + b_own0] = ov0;      // disjoint extension region
        sOv[h_own * 17 + b_own0 + 8] = ov1;
        __syncthreads();
        {   // coalesced outAll store via bounce (2 entries/thread)
            int e0 = tid, e1 = tid + 256;
            int hs0 = e0 >> 4, bs0 = e0 & 15;
            int hs1 = e1 >> 4, bs1 = e1 & 15;
            float* oa = g_outAll + (size_t)t * (HID * BATCH);
            oa[(size_t)(hgrp * 32 + hs0) * 64 + b0 + bs0] = sOv[hs0 * 17 + bs0];
            oa[(size_t)(hgrp * 32 + hs1) * 64 + b0 + bs1] = sOv[hs1 * 17 + bs1];
        }

        group_barrier(sense, bqg);       // 1000 flips/group (even) -> replay safe
    }
}

// ---- phase 3 (proven): y[t][b][o] = sum_j out[t][j][b]*eWoT[j][o]+bias
__global__ __launch_bounds__(256) void readout_kernel(const float* __restrict__ bo,
                                                      const float* __restrict__ bv,
                                                      float* __restrict__ y) {
    __shared__ float outS[64][64];
    const int t = blockIdx.x;
    const int tid = threadIdx.x;
    const int tx = tid & 15, ty = tid >> 4;
    const int b4 = tx * 4, o4 = ty * 4;
    const float* outT = g_outAll + (size_t)t * (HID * BATCH);

    unsigned long long acc[4][2];
#pragma unroll
    for (int i = 0; i < 4; i++) { acc[i][0] = 0ull; acc[i][1] = 0ull; }
    float accv[4] = {0.f, 0.f, 0.f, 0.f};

    for (int tile = 0; tile < 16; tile++) {
        __syncthreads();
#pragma unroll
        for (int k = 0; k < 4; k++) {
            int fid = tid + k * 256;
            ((float4*)&outS[0][0])[fid] = ((const float4*)(outT + (size_t)tile * 4096))[fid];
        }
        __syncthreads();
#pragma unroll 4
        for (int jj = 0; jj < 64; jj++) {
            int j = tile * 64 + jj;
            float4 ov = *(const float4*)&outS[jj][b4];
            ulonglong2 wq = __ldg((const ulonglong2*)(g_eWoT + (size_t)j * OPAD + o4));
            unsigned long long a0 = pk2(ov.x, ov.x), a1 = pk2(ov.y, ov.y);
            unsigned long long a2 = pk2(ov.z, ov.z), a3 = pk2(ov.w, ov.w);
            acc[0][0] = ffma2(a0, wq.x, acc[0][0]); acc[0][1] = ffma2(a0, wq.y, acc[0][1]);
            acc[1][0] = ffma2(a1, wq.x, acc[1][0]); acc[1][1] = ffma2(a1, wq.y, acc[1][1]);
            acc[2][0] = ffma2(a2, wq.x, acc[2][0]); acc[2][1] = ffma2(a2, wq.y, acc[2][1]);
            acc[3][0] = ffma2(a3, wq.x, acc[3][0]); acc[3][1] = ffma2(a3, wq.y, acc[3][1]);
            if (ty == 0) {
                float w64 = __ldg(g_eWoT + (size_t)j * OPAD + 64);
                accv[0] += ov.x * w64; accv[1] += ov.y * w64;
                accv[2] += ov.z * w64; accv[3] += ov.w * w64;
            }
        }
    }

    float* yt = y + (size_t)t * (BATCH * NY);
    const float bo0 = bo[o4], bo1 = bo[o4 + 1], bo2 = bo[o4 + 2], bo3 = bo[o4 + 3];
#pragma unroll
    for (int i = 0; i < 4; i++) {
        float f0, f1, f2, f3;
        upk2(acc[i][0], f0, f1);
        upk2(acc[i][1], f2, f3);
        float* yr = yt + (size_t)(b4 + i) * NY;
        yr[o4 + 0] = f0 + bo0; yr[o4 + 1] = f1 + bo1;
        yr[o4 + 2] = f2 + bo2; yr[o4 + 3] = f3 + bo3;
        if (ty == 0) yr[64] = accv[i] + bv[0];
    }
}

extern "C" void kernel_launch(void* const* d_in, const int* in_sizes, int n_in,
                              void* d_out, int out_size) {
    const float* x  = (const float*)d_in[0];
    const float* Wx = (const float*)d_in[1];
    const float* Wh = (const float*)d_in[2];
    const float* bh = (const float*)d_in[3];
    const float* Wo = (const float*)d_in[4];
    const float* bo = (const float*)d_in[5];
    const float* Wv = (const float*)d_in[6];
    const float* bv = (const float*)d_in[7];
    float* y = (float*)d_out;
    (void)in_sizes; (void)n_in; (void)out_size;

    {
        int total = HID * HID + NY * HID;
        prep_kernel<<<(total + 255) / 256, 256>>>(Wh, Wo, Wv);
    }
    xproj_kernel<<<dim3(HID / 128, T_STEPS), 256>>>(x, Wx);
    noop_kernel<<<1, 32>>>();   // keeps rnn_kernel in the profiled (4th) slot
    // 32*1028 weights + 16*1028 staging (sRedF aliases) + 544 sOv + pad = 199680 B
    static const int RNN_SMEM = (48 * WSTR + 576) * 4;
    cudaFuncSetAttribute(rnn_kernel, cudaFuncAttributeMaxDynamicSharedMemorySize, RNN_SMEM);
    rnn_kernel<<<NCTA, 256, RNN_SMEM>>>(bh);
    readout_kernel<<<T_STEPS, 256>>>(bo, bv, y);
}